// round 13
// baseline (speedup 1.0000x reference)
#include <cuda_runtime.h>

// EfficientGNN: 2-layer GCN + mean-over-nodes, algebraically collapsed.
// Multi-kernel, fence-free, SELF-CLEANING (no memset node: device globals
// start zeroed; each kernel zeroes what the next replay needs zeroed).
//   deg[c] += 1 per in-edge;  dinv = rsqrt(deg+1);  p = dinv*x
//   u[c] += p[r];  v[r] += dinv[c]           (random REDs, L2-resident)
//   s[i] = dinv*(p+u),  w[i] = dinv*(dinv+v)
//   t[f] = sum_i w[i]*relu(s[i]*W1[f]+b1[f]);  out = t@W2/N + b2

#define NMAX 100000
#define HID  128

__device__ float g_deg[NMAX];   // zeroed by k_dinv after read
__device__ float g_u[NMAX];     // zeroed by k_reduce after read
__device__ float g_v[NMAX];     // zeroed by k_reduce after read
__device__ float g_t[HID];      // zeroed by k_dinv (before k_reduce accumulates)
__device__ float g_p[NMAX];     // overwritten every launch
__device__ float g_dinv[NMAX];  // overwritten every launch

__global__ void k_deg(const int* __restrict__ col, int E) {
    int i = blockIdx.x * blockDim.x + threadIdx.x;
    int e0 = i * 8;
    if (e0 + 7 < E) {
        int4 a = *reinterpret_cast<const int4*>(col + e0);
        int4 b = *reinterpret_cast<const int4*>(col + e0 + 4);
        atomicAdd(&g_deg[a.x], 1.0f); atomicAdd(&g_deg[a.y], 1.0f);
        atomicAdd(&g_deg[a.z], 1.0f); atomicAdd(&g_deg[a.w], 1.0f);
        atomicAdd(&g_deg[b.x], 1.0f); atomicAdd(&g_deg[b.y], 1.0f);
        atomicAdd(&g_deg[b.z], 1.0f); atomicAdd(&g_deg[b.w], 1.0f);
    } else {
        for (int e = e0; e < E; ++e) atomicAdd(&g_deg[col[e]], 1.0f);
    }
}

__global__ void k_dinv(const float* __restrict__ x, int n) {
    int i = blockIdx.x * blockDim.x + threadIdx.x;
    if (i < n) {
        float d = rsqrtf(g_deg[i] + 1.0f);   // +1 self loop
        g_deg[i]  = 0.0f;                    // self-clean for next replay
        g_dinv[i] = d;
        g_p[i]    = d * x[i];
    }
    if (i < HID) g_t[i] = 0.0f;              // ready for k_reduce
}

__global__ void k_edge(const int* __restrict__ row, const int* __restrict__ col, int E) {
    int i = blockIdx.x * blockDim.x + threadIdx.x;
    int e0 = i * 8;
    if (e0 + 7 < E) {
        int4 ra = *reinterpret_cast<const int4*>(row + e0);
        int4 rb = *reinterpret_cast<const int4*>(row + e0 + 4);
        int4 ca = *reinterpret_cast<const int4*>(col + e0);
        int4 cb = *reinterpret_cast<const int4*>(col + e0 + 4);
        // all gathers first (MLP), then REDs
        float p0 = g_p[ra.x], p1 = g_p[ra.y], p2 = g_p[ra.z], p3 = g_p[ra.w];
        float p4 = g_p[rb.x], p5 = g_p[rb.y], p6 = g_p[rb.z], p7 = g_p[rb.w];
        float d0 = g_dinv[ca.x], d1 = g_dinv[ca.y], d2 = g_dinv[ca.z], d3 = g_dinv[ca.w];
        float d4 = g_dinv[cb.x], d5 = g_dinv[cb.y], d6 = g_dinv[cb.z], d7 = g_dinv[cb.w];
        atomicAdd(&g_u[ca.x], p0); atomicAdd(&g_u[ca.y], p1);
        atomicAdd(&g_u[ca.z], p2); atomicAdd(&g_u[ca.w], p3);
        atomicAdd(&g_u[cb.x], p4); atomicAdd(&g_u[cb.y], p5);
        atomicAdd(&g_u[cb.z], p6); atomicAdd(&g_u[cb.w], p7);
        atomicAdd(&g_v[ra.x], d0); atomicAdd(&g_v[ra.y], d1);
        atomicAdd(&g_v[ra.z], d2); atomicAdd(&g_v[ra.w], d3);
        atomicAdd(&g_v[rb.x], d4); atomicAdd(&g_v[rb.y], d5);
        atomicAdd(&g_v[rb.z], d6); atomicAdd(&g_v[rb.w], d7);
    } else {
        for (int e = e0; e < E; ++e) {
            int r = row[e], c = col[e];
            atomicAdd(&g_u[c], g_p[r]);
            atomicAdd(&g_v[r], g_dinv[c]);
        }
    }
}

// One 128-node tile per block (grid ~782 for occupancy); threads = (feature f, node-half).
// Inner loop reads TWO nodes per LDS.128. Zeroes u,v after reading (self-clean).
__global__ void __launch_bounds__(256)
k_reduce(const float* __restrict__ W1, const float* __restrict__ b1, int n) {
    __shared__ float2 sh[128];         // {s, w} per node
    __shared__ float  red[2 * HID];
    int tid  = threadIdx.x;
    int f    = tid & (HID - 1);
    int half = tid >> 7;

    if (tid < 128) {
        int i = blockIdx.x * 128 + tid;
        float2 swv = make_float2(0.0f, 0.0f);
        if (i < n) {
            float d = g_dinv[i];
            swv.x = d * (g_p[i] + g_u[i]);
            swv.y = d * (d + g_v[i]);
            g_u[i] = 0.0f;             // self-clean
            g_v[i] = 0.0f;
        }
        sh[tid] = swv;
    }
    __syncthreads();

    float W1f = W1[f];
    float b1f = b1[f];
    float a0 = 0.f, a1 = 0.f, a2 = 0.f, a3 = 0.f;
    const float4* shh = reinterpret_cast<const float4*>(sh + half * 64);  // 32 float4 = 64 nodes
    #pragma unroll
    for (int j = 0; j < 32; j += 4) {
        float4 q0 = shh[j + 0];    // {s0,w0,s1,w1}
        float4 q1 = shh[j + 1];
        float4 q2 = shh[j + 2];
        float4 q3 = shh[j + 3];
        a0 += q0.y * fmaxf(fmaf(q0.x, W1f, b1f), 0.0f);
        a1 += q0.w * fmaxf(fmaf(q0.z, W1f, b1f), 0.0f);
        a2 += q1.y * fmaxf(fmaf(q1.x, W1f, b1f), 0.0f);
        a3 += q1.w * fmaxf(fmaf(q1.z, W1f, b1f), 0.0f);
        a0 += q2.y * fmaxf(fmaf(q2.x, W1f, b1f), 0.0f);
        a1 += q2.w * fmaxf(fmaf(q2.z, W1f, b1f), 0.0f);
        a2 += q3.y * fmaxf(fmaf(q3.x, W1f, b1f), 0.0f);
        a3 += q3.w * fmaxf(fmaf(q3.z, W1f, b1f), 0.0f);
    }
    red[half * HID + f] = (a0 + a1) + (a2 + a3);
    __syncthreads();
    if (tid < HID)
        atomicAdd(&g_t[tid], red[tid] + red[HID + tid]);
}

// 4 blocks x 128 threads: one output element per thread, W2 reads coalesced.
__global__ void __launch_bounds__(128)
k_out(const float* __restrict__ W2, const float* __restrict__ b2,
      float* __restrict__ out, int n, int odim) {
    __shared__ float sh_t[HID];
    int tid = threadIdx.x;
    sh_t[tid] = g_t[tid];
    __syncthreads();
    int k = blockIdx.x * 128 + tid;
    if (k < odim) {
        float a = 0.0f;
        #pragma unroll 16
        for (int f = 0; f < HID; ++f)
            a = fmaf(sh_t[f], W2[f * odim + k], a);
        out[k] = a * (1.0f / (float)n) + b2[k];
    }
}

extern "C" void kernel_launch(void* const* d_in, const int* in_sizes, int n_in,
                              void* d_out, int out_size) {
    const float* x   = (const float*)d_in[0];
    const int*   ei  = (const int*)  d_in[1];
    const float* W1  = (const float*)d_in[2];
    const float* b1  = (const float*)d_in[3];
    const float* W2  = (const float*)d_in[4];
    const float* b2  = (const float*)d_in[5];
    float*       out = (float*)d_out;

    int n = in_sizes[0];
    int E = in_sizes[1] / 2;
    const int* row = ei;
    const int* col = ei + E;
    int odim = out_size;

    int tb = 256;
    int e8 = (E + 7) / 8;
    k_deg   <<<(e8 + tb - 1) / tb, tb>>>(col, E);
    k_dinv  <<<(n + tb - 1) / tb, tb>>>(x, n);
    k_edge  <<<(e8 + tb - 1) / tb, tb>>>(row, col, E);
    k_reduce<<<(n + 127) / 128, 256>>>(W1, b1, n);
    k_out   <<<(odim + 127) / 128, 128>>>(W2, b2, out, n, odim);
}